// round 6
// baseline (speedup 1.0000x reference)
#include <cuda_runtime.h>

#define NCAM 6
#define CCH  128
#define H0   32
#define W0   88
#define H1   16
#define W1   44
#define HW0  (H0*W0)      // 2816
#define HW1  (H1*W1)      // 704
#define QDIM 16384
#define PPTS 4
#define NTASK (QDIM * PPTS)
#define EPSF 1e-5f
#define FULLMASK 0xffffffffu

// Transposed feature scratch: [N, H, W, C] so channel gathers are contiguous.
__device__ float g_f0t[NCAM * HW0 * CCH];   // ~8.65 MB
__device__ float g_f1t[NCAM * HW1 * CCH];   // ~2.16 MB

// -------------------------------------------------------------------------
// SMEM-tiled transpose with float4 I/O: [C=128, HW] -> [HW, C] per camera.
// Each thread: 1 LDG.128 (4 hw, 1 c) -> smem -> 1 STG.128 (1 hw, 4 c).
// -------------------------------------------------------------------------
#define NBLK0 (NCAM * 4 * (HW0/32))   // 2112
#define NBLK1 (NCAM * 4 * (HW1/32))   // 528

__global__ void __launch_bounds__(256)
transpose_feats_kernel(const float* __restrict__ f0,
                       const float* __restrict__ f1) {
    __shared__ float tile[32][33];

    int b = blockIdx.x;
    const float* __restrict__ src;
    float* __restrict__ dst;
    int n, ct, hwt, HW;
    if (b < NBLK0) {
        n = b / (4 * (HW0/32));
        int r = b % (4 * (HW0/32));
        ct = r & 3; hwt = r >> 2;
        src = f0; dst = g_f0t; HW = HW0;
    } else {
        b -= NBLK0;
        n = b / (4 * (HW1/32));
        int r = b % (4 * (HW1/32));
        ct = r & 3; hwt = r >> 2;
        src = f1; dst = g_f1t; HW = HW1;
    }

    // Read: thread -> c = tid>>3 (0..31), hw4 = (tid&7)*4
    {
        int c   = threadIdx.x >> 3;
        int hw4 = (threadIdx.x & 7) * 4;
        const float4 v = *reinterpret_cast<const float4*>(
            src + (size_t)n * CCH * HW + (size_t)(ct*32 + c) * HW + hwt*32 + hw4);
        tile[hw4 + 0][c] = v.x;
        tile[hw4 + 1][c] = v.y;
        tile[hw4 + 2][c] = v.z;
        tile[hw4 + 3][c] = v.w;
    }
    __syncthreads();

    // Write: thread -> hw = tid>>3 (0..31), c4 = (tid&7)*4
    {
        int hw = threadIdx.x >> 3;
        int c4 = (threadIdx.x & 7) * 4;
        float4 v;
        v.x = tile[hw][c4 + 0];
        v.y = tile[hw][c4 + 1];
        v.z = tile[hw][c4 + 2];
        v.w = tile[hw][c4 + 3];
        *reinterpret_cast<float4*>(
            dst + (size_t)n * HW * CCH + (size_t)(hwt*32 + hw) * CCH + ct*32 + c4) = v;
    }
}

// -------------------------------------------------------------------------
// Main sampling kernel: 2 tasks per warp; lane owns 4 channels.
// Lanes 0-5 project task A's cams; lanes 8-13 project task B's cams.
// -------------------------------------------------------------------------

// Packed f32x2 weighted accumulate of 4 contiguous floats at base+byteoff.
__device__ __forceinline__ void gacc(const char* __restrict__ base, int byteoff,
                                     float w,
                                     unsigned long long& aA, unsigned long long& aB) {
    ulonglong2 v = *reinterpret_cast<const ulonglong2*>(base + byteoff);
    unsigned long long wp;
    asm("mov.b64 %0, {%1, %1};" : "=l"(wp) : "f"(w));
    asm("fma.rn.f32x2 %0, %1, %2, %0;" : "+l"(aA) : "l"(v.x), "l"(wp));
    asm("fma.rn.f32x2 %0, %1, %2, %0;" : "+l"(aB) : "l"(v.y), "l"(wp));
}

// Inline bilinear sample of one level; u,v warp-uniform.
__device__ __forceinline__ void sample_level(const char* __restrict__ base,
                                             float u, float v, int cam,
                                             int Wl, int Hl,
                                             unsigned long long& aA,
                                             unsigned long long& aB) {
    float px = u * (float)Wl - 0.5f;
    float py = v * (float)Hl - 0.5f;
    float x0f = floorf(px);
    float y0f = floorf(py);
    float wx1 = px - x0f, wx0 = 1.0f - wx1;
    float wy1 = py - y0f, wy0 = 1.0f - wy1;
    int x0 = (int)x0f, y0 = (int)y0f;
    int x1 = x0 + 1,   y1 = y0 + 1;
    if (x0 < 0)      { wx0 = 0.0f; x0 = 0; }
    if (x1 > Wl - 1) { wx1 = 0.0f; x1 = Wl - 1; }
    if (y0 < 0)      { wy0 = 0.0f; y0 = 0; }
    if (y1 > Hl - 1) { wy1 = 0.0f; y1 = Hl - 1; }
    int cambase = cam * Hl * Wl;
    int r0 = (cambase + y0 * Wl) * (CCH * 4);   // byte offsets
    int r1 = (cambase + y1 * Wl) * (CCH * 4);
    int c0 = x0 * (CCH * 4);
    int c1 = x1 * (CCH * 4);
    gacc(base, r0 + c0, wx0 * wy0, aA, aB);
    gacc(base, r0 + c1, wx1 * wy0, aA, aB);
    gacc(base, r1 + c0, wx0 * wy1, aA, aB);
    gacc(base, r1 + c1, wx1 * wy1, aA, aB);
}

__global__ void __launch_bounds__(256, 8)
bev_sample_kernel(const float* __restrict__ refpts,
                  const float* __restrict__ lidar2img,
                  float* __restrict__ out) {
    __shared__ float sM[NCAM * 16];
    if (threadIdx.x < NCAM * 16) sM[threadIdx.x] = lidar2img[threadIdx.x];
    __syncthreads();

    int wpair = blockIdx.x * 8 + (threadIdx.x >> 5);   // warp id = task pair
    int lane  = threadIdx.x & 31;
    int t0 = wpair * 2;
    int which = (lane >> 3) & 1;        // 0: lanes 0-7/16-23, 1: lanes 8-15/24-31
    int cam   = lane & 7;
    int task  = t0 + which;

    // Projection: lanes 0-5 -> task A, lanes 8-13 -> task B.
    bool valid = false;
    float u = 0.f, v = 0.f;
    if (lane < 16 && cam < NCAM) {
        int q = task >> 2;
        int p = task & 3;
        int hb = q >> 7;
        int wb = q & 127;
        const float* rp = refpts + ((size_t)((p * 128 + hb) * 128 + wb)) * 3;
        float X = __ldg(rp + 0) * 102.4f - 51.2f;
        float Y = __ldg(rp + 1) * 102.4f - 51.2f;
        float Z = __ldg(rp + 2) * 8.0f  - 5.0f;

        const float* M = sM + cam * 16;
        float cz = fmaf(M[8], X, fmaf(M[9], Y, fmaf(M[10], Z, M[11])));
        if (cz > EPSF) {
            float cx = fmaf(M[0], X, fmaf(M[1], Y, fmaf(M[2], Z, M[3])));
            float cy = fmaf(M[4], X, fmaf(M[5], Y, fmaf(M[6], Z, M[7])));
            float invz = __fdividef(1.0f, cz);
            u = cx * invz * (1.0f / 704.0f);
            v = cy * invz * (1.0f / 256.0f);
            valid = (u > 0.0f) & (u < 1.0f) & (v > 0.0f) & (v < 1.0f);
        }
    }

    unsigned vm  = __ballot_sync(FULLMASK, valid);
    unsigned vmA = vm & 0x3Fu;
    unsigned vmB = (vm >> 8) & 0x3Fu;

    const char* b0 = (const char*)g_f0t + lane * 16;   // lane channel offset
    const char* b1 = (const char*)g_f1t + lane * 16;

    // ---------------- Task A ----------------
    {
        unsigned long long aA = 0ull, aB = 0ull;
        int cnt = __popc(vmA);
#pragma unroll
        for (int c = 0; c < NCAM; c++) {
            if (vmA & (1u << c)) {
                float uu = __shfl_sync(FULLMASK, u, c);
                float vv = __shfl_sync(FULLMASK, v, c);
                sample_level(b0, uu, vv, c, W0, H0, aA, aB);
                sample_level(b1, uu, vv, c, W1, H1, aA, aB);
            }
        }
        float scale = 0.5f / fmaxf((float)cnt, 1.0f);
        float ax, ay, az, aw;
        asm("mov.b64 {%0, %1}, %2;" : "=f"(ax), "=f"(ay) : "l"(aA));
        asm("mov.b64 {%0, %1}, %2;" : "=f"(az), "=f"(aw) : "l"(aB));
        float4 o;
        o.x = ax * scale; o.y = ay * scale;
        o.z = az * scale; o.w = aw * scale;
        *reinterpret_cast<float4*>(out + (size_t)t0 * CCH + lane * 4) = o;
    }

    // ---------------- Task B ----------------
    {
        unsigned long long aA = 0ull, aB = 0ull;
        int cnt = __popc(vmB);
#pragma unroll
        for (int c = 0; c < NCAM; c++) {
            if (vmB & (1u << c)) {
                float uu = __shfl_sync(FULLMASK, u, c + 8);
                float vv = __shfl_sync(FULLMASK, v, c + 8);
                sample_level(b0, uu, vv, c, W0, H0, aA, aB);
                sample_level(b1, uu, vv, c, W1, H1, aA, aB);
            }
        }
        float scale = 0.5f / fmaxf((float)cnt, 1.0f);
        float ax, ay, az, aw;
        asm("mov.b64 {%0, %1}, %2;" : "=f"(ax), "=f"(ay) : "l"(aA));
        asm("mov.b64 {%0, %1}, %2;" : "=f"(az), "=f"(aw) : "l"(aB));
        float4 o;
        o.x = ax * scale; o.y = ay * scale;
        o.z = az * scale; o.w = aw * scale;
        *reinterpret_cast<float4*>(out + (size_t)(t0 + 1) * CCH + lane * 4) = o;
    }
}

extern "C" void kernel_launch(void* const* d_in, const int* in_sizes, int n_in,
                              void* d_out, int out_size) {
    const float* refpts    = (const float*)d_in[0];   // [1,4,128,128,3]
    const float* feats0    = (const float*)d_in[1];   // [1,6,128,32,88]
    const float* feats1    = (const float*)d_in[2];   // [1,6,128,16,44]
    const float* lidar2img = (const float*)d_in[3];   // [1,6,4,4]
    float* out = (float*)d_out;                       // [1,16384,4,128]

    transpose_feats_kernel<<<NBLK0 + NBLK1, 256>>>(feats0, feats1);
    // 2 tasks per warp, 8 warps per block
    bev_sample_kernel<<<NTASK / 16, 256>>>(refpts, lidar2img, out);
}

// round 7
// speedup vs baseline: 1.1199x; 1.1199x over previous
#include <cuda_runtime.h>

#define NCAM 6
#define CCH  128
#define H0   32
#define W0   88
#define H1   16
#define W1   44
#define H0P  (H0+2)       // 34
#define W0P  (W0+2)       // 90
#define H1P  (H1+2)       // 18
#define W1P  (W1+2)       // 46
#define HW0  (H0*W0)      // 2816
#define HW1  (H1*W1)      // 704
#define QDIM 16384
#define PPTS 4
#define NTASK (QDIM * PPTS)
#define EPSF 1e-5f
#define FULLMASK 0xffffffffu

// Transposed + zero-padded feature scratch: [N, H+2, W+2, C].
// Borders are never written; __device__ globals are zero-initialized at
// module load, so out-of-range bilinear corners read exact zeros.
__device__ float g_f0t[NCAM * H0P * W0P * CCH];   // ~9.4 MB
__device__ float g_f1t[NCAM * H1P * W1P * CCH];   // ~2.5 MB

// -------------------------------------------------------------------------
// SMEM-tiled transpose with float4 I/O: [C=128, HW] -> padded [H+2, W+2, C].
// -------------------------------------------------------------------------
#define NBLK0 (NCAM * 4 * (HW0/32))   // 2112
#define NBLK1 (NCAM * 4 * (HW1/32))   // 528

__global__ void __launch_bounds__(256)
transpose_feats_kernel(const float* __restrict__ f0,
                       const float* __restrict__ f1) {
    __shared__ float tile[32][33];

    int b = blockIdx.x;
    const float* __restrict__ src;
    float* __restrict__ dst;
    int n, ct, hwt, HW, W, WP;
    if (b < NBLK0) {
        n = b / (4 * (HW0/32));
        int r = b % (4 * (HW0/32));
        ct = r & 3; hwt = r >> 2;
        src = f0; dst = g_f0t; HW = HW0; W = W0; WP = W0P;
    } else {
        b -= NBLK0;
        n = b / (4 * (HW1/32));
        int r = b % (4 * (HW1/32));
        ct = r & 3; hwt = r >> 2;
        src = f1; dst = g_f1t; HW = HW1; W = W1; WP = W1P;
    }

    // Read: thread -> c = tid>>3 (0..31), hw4 = (tid&7)*4
    {
        int c   = threadIdx.x >> 3;
        int hw4 = (threadIdx.x & 7) * 4;
        const float4 v = *reinterpret_cast<const float4*>(
            src + (size_t)n * CCH * HW + (size_t)(ct*32 + c) * HW + hwt*32 + hw4);
        tile[hw4 + 0][c] = v.x;
        tile[hw4 + 1][c] = v.y;
        tile[hw4 + 2][c] = v.z;
        tile[hw4 + 3][c] = v.w;
    }
    __syncthreads();

    // Write: thread -> hw = tid>>3 (0..31), c4 = (tid&7)*4. Padded dst.
    {
        int hw = threadIdx.x >> 3;
        int c4 = (threadIdx.x & 7) * 4;
        float4 v;
        v.x = tile[hw][c4 + 0];
        v.y = tile[hw][c4 + 1];
        v.z = tile[hw][c4 + 2];
        v.w = tile[hw][c4 + 3];
        int hwglob = hwt * 32 + hw;
        int h = hwglob / W;
        int w = hwglob - h * W;
        size_t HPWP = (size_t)(W == W0 ? H0P * W0P : H1P * W1P);
        size_t off = ((size_t)n * HPWP + (size_t)(h + 1) * WP + (w + 1)) * CCH
                   + ct * 32 + c4;
        *reinterpret_cast<float4*>(dst + off) = v;
    }
}

// -------------------------------------------------------------------------
// Main sampling kernel: 2 tasks per warp; lane owns 4 channels.
// Lanes 0-5 project task A's cams; lanes 8-13 project task B's cams.
// -------------------------------------------------------------------------

// Packed f32x2 weighted accumulate of 4 contiguous floats at base+byteoff.
__device__ __forceinline__ void gacc(const char* __restrict__ base, int byteoff,
                                     float w,
                                     unsigned long long& aA, unsigned long long& aB) {
    ulonglong2 v = *reinterpret_cast<const ulonglong2*>(base + byteoff);
    unsigned long long wp;
    asm("mov.b64 %0, {%1, %1};" : "=l"(wp) : "f"(w));
    asm("fma.rn.f32x2 %0, %1, %2, %0;" : "+l"(aA) : "l"(v.x), "l"(wp));
    asm("fma.rn.f32x2 %0, %1, %2, %0;" : "+l"(aB) : "l"(v.y), "l"(wp));
}

// Clamp-free bilinear sample of one padded level; u,v warp-uniform.
// cambase = cam * HP * WP (element index). px = u*W + 0.5 maps into padded
// coords; all 4 corners are in-bounds; border corners read zeros.
__device__ __forceinline__ void sample_level(const char* __restrict__ base,
                                             float u, float v, int cambase,
                                             int Wl, int Hl, int WP,
                                             unsigned long long& aA,
                                             unsigned long long& aB) {
    float px = fmaf(u, (float)Wl, 0.5f);
    float py = fmaf(v, (float)Hl, 0.5f);
    int x0 = __float2int_rd(px);
    int y0 = __float2int_rd(py);
    float wx1 = px - __int2float_rn(x0);
    float wy1 = py - __int2float_rn(y0);
    float wx0 = 1.0f - wx1;
    float wy0 = 1.0f - wy1;

    int o00 = (cambase + y0 * WP + x0) << 9;   // *CCH*4 bytes
    int rowB = WP << 9;
    gacc(base, o00,              wx0 * wy0, aA, aB);
    gacc(base, o00 + 512,        wx1 * wy0, aA, aB);
    gacc(base, o00 + rowB,       wx0 * wy1, aA, aB);
    gacc(base, o00 + rowB + 512, wx1 * wy1, aA, aB);
}

__global__ void __launch_bounds__(256, 8)
bev_sample_kernel(const float* __restrict__ refpts,
                  const float* __restrict__ lidar2img,
                  float* __restrict__ out) {
    __shared__ float sM[NCAM * 16];
    if (threadIdx.x < NCAM * 16) sM[threadIdx.x] = lidar2img[threadIdx.x];
    __syncthreads();

    int wpair = blockIdx.x * 8 + (threadIdx.x >> 5);   // warp id = task pair
    int lane  = threadIdx.x & 31;
    int t0 = wpair * 2;
    int which = (lane >> 3) & 1;
    int cam   = lane & 7;
    int task  = t0 + which;

    // Projection: lanes 0-5 -> task A, lanes 8-13 -> task B.
    bool valid = false;
    float u = 0.f, v = 0.f;
    if (lane < 16 && cam < NCAM) {
        int q = task >> 2;
        int p = task & 3;
        int hb = q >> 7;
        int wb = q & 127;
        const float* rp = refpts + ((size_t)((p * 128 + hb) * 128 + wb)) * 3;
        float X = __ldg(rp + 0) * 102.4f - 51.2f;
        float Y = __ldg(rp + 1) * 102.4f - 51.2f;
        float Z = __ldg(rp + 2) * 8.0f  - 5.0f;

        const float* M = sM + cam * 16;
        float cz = fmaf(M[8], X, fmaf(M[9], Y, fmaf(M[10], Z, M[11])));
        if (cz > EPSF) {
            float cx = fmaf(M[0], X, fmaf(M[1], Y, fmaf(M[2], Z, M[3])));
            float cy = fmaf(M[4], X, fmaf(M[5], Y, fmaf(M[6], Z, M[7])));
            float invz = __fdividef(1.0f, cz);
            u = cx * invz * (1.0f / 704.0f);
            v = cy * invz * (1.0f / 256.0f);
            valid = (u > 0.0f) & (u < 1.0f) & (v > 0.0f) & (v < 1.0f);
        }
    }

    unsigned vm  = __ballot_sync(FULLMASK, valid);
    unsigned vmA = vm & 0x3Fu;
    unsigned vmB = (vm >> 8) & 0x3Fu;

    const char* b0 = (const char*)g_f0t + lane * 16;   // lane channel offset
    const char* b1 = (const char*)g_f1t + lane * 16;

    // ---------------- Task A ----------------
    {
        unsigned long long aA = 0ull, aB = 0ull;
        int cnt = __popc(vmA);
#pragma unroll
        for (int c = 0; c < NCAM; c++) {
            if (vmA & (1u << c)) {
                float uu = __shfl_sync(FULLMASK, u, c);
                float vv = __shfl_sync(FULLMASK, v, c);
                sample_level(b0, uu, vv, c * (H0P * W0P), W0, H0, W0P, aA, aB);
                sample_level(b1, uu, vv, c * (H1P * W1P), W1, H1, W1P, aA, aB);
            }
        }
        float scale = 0.5f / fmaxf((float)cnt, 1.0f);
        float ax, ay, az, aw;
        asm("mov.b64 {%0, %1}, %2;" : "=f"(ax), "=f"(ay) : "l"(aA));
        asm("mov.b64 {%0, %1}, %2;" : "=f"(az), "=f"(aw) : "l"(aB));
        float4 o;
        o.x = ax * scale; o.y = ay * scale;
        o.z = az * scale; o.w = aw * scale;
        *reinterpret_cast<float4*>(out + (size_t)t0 * CCH + lane * 4) = o;
    }

    // ---------------- Task B ----------------
    {
        unsigned long long aA = 0ull, aB = 0ull;
        int cnt = __popc(vmB);
#pragma unroll
        for (int c = 0; c < NCAM; c++) {
            if (vmB & (1u << c)) {
                float uu = __shfl_sync(FULLMASK, u, c + 8);
                float vv = __shfl_sync(FULLMASK, v, c + 8);
                sample_level(b0, uu, vv, c * (H0P * W0P), W0, H0, W0P, aA, aB);
                sample_level(b1, uu, vv, c * (H1P * W1P), W1, H1, W1P, aA, aB);
            }
        }
        float scale = 0.5f / fmaxf((float)cnt, 1.0f);
        float ax, ay, az, aw;
        asm("mov.b64 {%0, %1}, %2;" : "=f"(ax), "=f"(ay) : "l"(aA));
        asm("mov.b64 {%0, %1}, %2;" : "=f"(az), "=f"(aw) : "l"(aB));
        float4 o;
        o.x = ax * scale; o.y = ay * scale;
        o.z = az * scale; o.w = aw * scale;
        *reinterpret_cast<float4*>(out + (size_t)(t0 + 1) * CCH + lane * 4) = o;
    }
}

extern "C" void kernel_launch(void* const* d_in, const int* in_sizes, int n_in,
                              void* d_out, int out_size) {
    const float* refpts    = (const float*)d_in[0];   // [1,4,128,128,3]
    const float* feats0    = (const float*)d_in[1];   // [1,6,128,32,88]
    const float* feats1    = (const float*)d_in[2];   // [1,6,128,16,44]
    const float* lidar2img = (const float*)d_in[3];   // [1,6,4,4]
    float* out = (float*)d_out;                       // [1,16384,4,128]

    transpose_feats_kernel<<<NBLK0 + NBLK1, 256>>>(feats0, feats1);
    bev_sample_kernel<<<NTASK / 16, 256>>>(refpts, lidar2img, out);
}